// round 10
// baseline (speedup 1.0000x reference)
#include <cuda_runtime.h>
#include <cuda_bf16.h>
#include <cuda_fp16.h>
#include <cstdint>

#define NNODES 50000
#define HIDDEN 128
#define MLPD   64
#define SA 136   // padded bf16 row stride: 8-row ldmatrix steps tile all banks

// Per-node precomputed table (fp16):
//   T[n][0:64]   = emb[n] @ W1[0:128,:]  + b1   (src half, bias folded in)
//   T[n][64:128] = emb[n] @ W1[128:256,:]       (dst half)
__device__ __half g_Th[(size_t)NNODES * HIDDEN];
__device__ int g_is64;   // 1 if edge_index buffer is int64, 0 if int32

__device__ __forceinline__ uint32_t pkbf(__nv_bfloat16 a, __nv_bfloat16 b) {
    __nv_bfloat162 t = __halves2bfloat162(a, b);
    return *reinterpret_cast<uint32_t*>(&t);
}
__device__ __forceinline__ uint32_t smem_u32(const void* p) {
    return (uint32_t)__cvta_generic_to_shared(p);
}
__device__ __forceinline__ void ldsm_x4(uint32_t& r0, uint32_t& r1,
                                        uint32_t& r2, uint32_t& r3, uint32_t addr) {
    asm volatile("ldmatrix.sync.aligned.m8n8.x4.shared.b16 {%0,%1,%2,%3}, [%4];"
                 : "=r"(r0), "=r"(r1), "=r"(r2), "=r"(r3) : "r"(addr));
}
__device__ __forceinline__ void mma16816(float* d, const uint32_t* a, const uint32_t* b) {
    asm volatile(
        "mma.sync.aligned.m16n8k16.row.col.f32.bf16.bf16.f32 "
        "{%0,%1,%2,%3}, {%4,%5,%6,%7}, {%8,%9}, {%0,%1,%2,%3};"
        : "+f"(d[0]), "+f"(d[1]), "+f"(d[2]), "+f"(d[3])
        : "r"(a[0]), "r"(a[1]), "r"(a[2]), "r"(a[3]), "r"(b[0]), "r"(b[1]));
}

// ---------------------------------------------------------------------------
// Kernel 1: T = emb @ Wc (+b1 on cols 0..63) via bf16 3-GEMM split on HMMA.
//   Wc[k][c] = (c<64) ? W1[k][c] : W1[128+k][c-64]
//   T ≈ Eh@Wh + Eh@Wl + El@Wh   (El@Wl dropped, ~2^-18 relative)
// Block: 128 nodes x 128 cols, 256 threads = 8 warps (4m x 2n). fp16 output.
// W1 is staged into smem (coalesced) and converted in-block — no extra launch.
// Block 0 additionally runs the edge-index dtype probe.
// ---------------------------------------------------------------------------
__global__ void __launch_bounds__(256, 1)
precompute_kernel(const float* __restrict__ emb, const float* __restrict__ W1,
                  const float* __restrict__ b1,
                  const long long* __restrict__ eidx64, int twoE) {
    extern __shared__ char smem[];
    __nv_bfloat16* sAh = (__nv_bfloat16*)smem;           // [128][SA]
    __nv_bfloat16* sAl = sAh + 128 * SA;
    __nv_bfloat16* sBh = sAl + 128 * SA;                 // [c=128][SA] (k contiguous)
    __nv_bfloat16* sBl = sBh + 128 * SA;
    float* sF = (float*)(sBl + 128 * SA);                // W1 fp32 stage (64 KB)

    const int t = threadIdx.x;
    const int n0 = blockIdx.x * 128;

    // --- dtype probe (block 0 only): 1024 int64 words (8 KB) is in-bounds
    // under both int32 and int64 interpretations of the buffer.
    if (blockIdx.x == 0) {
        __shared__ int ok;
        if (t == 0) ok = 1;
        __syncthreads();
        int n = twoE < 1024 ? twoE : 1024;
        for (int i = t; i < n; i += 256) {
            long long v = eidx64[i];
            if (v < 0 || v >= NNODES) ok = 0;
        }
        __syncthreads();
        if (t == 0) g_is64 = ok;
    }

    // Stage W1 (16384 floats) coalesced into sF
    for (int i = t; i < 4096; i += 256)
        ((float4*)sF)[i] = ((const float4*)W1)[i];

    // A loader: emb tile -> bf16 hi/lo, rows node-major, k contiguous
    for (int i = t; i < 128 * 32; i += 256) {
        int row = i >> 5, c4 = i & 31;
        int gn = n0 + row;
        float4 v = (gn < NNODES)
            ? *(const float4*)&emb[(size_t)gn * HIDDEN + c4 * 4]
            : make_float4(0.f, 0.f, 0.f, 0.f);
        __nv_bfloat16 hx = __float2bfloat16(v.x), hy = __float2bfloat16(v.y);
        __nv_bfloat16 hz = __float2bfloat16(v.z), hw = __float2bfloat16(v.w);
        __nv_bfloat16 lx = __float2bfloat16(v.x - __bfloat162float(hx));
        __nv_bfloat16 ly = __float2bfloat16(v.y - __bfloat162float(hy));
        __nv_bfloat16 lz = __float2bfloat16(v.z - __bfloat162float(hz));
        __nv_bfloat16 lw = __float2bfloat16(v.w - __bfloat162float(hw));
        *(uint2*)&sAh[row * SA + c4 * 4] = make_uint2(pkbf(hx, hy), pkbf(hz, hw));
        *(uint2*)&sAl[row * SA + c4 * 4] = make_uint2(pkbf(lx, ly), pkbf(lz, lw));
    }
    __syncthreads();

    // Convert Wc^T hi/lo into padded smem: reads conflict-free, stores ~4-way
    for (int i = t; i < 128 * 128; i += 256) {
        int c = i & 127, k = i >> 7;
        float w = (c < MLPD) ? sF[k * MLPD + c]
                             : sF[HIDDEN * MLPD + k * MLPD + (c - MLPD)];
        __nv_bfloat16 h = __float2bfloat16(w);
        sBh[c * SA + k] = h;
        sBl[c * SA + k] = __float2bfloat16(w - __bfloat162float(h));
    }
    __syncthreads();

    const int lane = t & 31;
    const int wid = t >> 5;
    const int wm = wid & 3;   // rows wm*32 .. +32
    const int wn = wid >> 2;  // cols wn*64 .. +64

    const int aRow = lane & 15, aKh = (lane >> 4) * 8;
    const int bN = (lane & 7) + ((lane >> 4) << 3), bKh = ((lane >> 3) & 1) * 8;

    float acc[2][8][4];
#pragma unroll
    for (int tm = 0; tm < 2; tm++)
#pragma unroll
        for (int tn = 0; tn < 8; tn++)
#pragma unroll
            for (int q = 0; q < 4; q++) acc[tm][tn][q] = 0.f;

#pragma unroll
    for (int pass = 0; pass < 3; pass++) {
        const __nv_bfloat16* pA = (pass == 2) ? sAl : sAh;
        const __nv_bfloat16* pB = (pass == 1) ? sBl : sBh;
#pragma unroll
        for (int k0 = 0; k0 < 128; k0 += 16) {
            uint32_t a[2][4], b[8][2];
#pragma unroll
            for (int tm = 0; tm < 2; tm++) {
                uint32_t ad = smem_u32(&pA[(wm * 32 + tm * 16 + aRow) * SA + k0 + aKh]);
                ldsm_x4(a[tm][0], a[tm][1], a[tm][2], a[tm][3], ad);
            }
#pragma unroll
            for (int tp = 0; tp < 4; tp++) {
                uint32_t bd = smem_u32(&pB[(wn * 64 + tp * 16 + bN) * SA + k0 + bKh]);
                ldsm_x4(b[2 * tp][0], b[2 * tp][1], b[2 * tp + 1][0], b[2 * tp + 1][1], bd);
            }
#pragma unroll
            for (int tm = 0; tm < 2; tm++)
#pragma unroll
                for (int tn = 0; tn < 8; tn++)
                    mma16816(acc[tm][tn], a[tm], b[tn]);
        }
    }

    // Epilogue: add b1 on cols<64, store fp16 (half2) to g_Th
    const int g = lane >> 2, tig = lane & 3;
#pragma unroll
    for (int tm = 0; tm < 2; tm++) {
#pragma unroll
        for (int tn = 0; tn < 8; tn++) {
            int col = wn * 64 + tn * 8 + 2 * tig;
            float bx = 0.f, by = 0.f;
            if (wn == 0) { bx = b1[col]; by = b1[col + 1]; }
            int row0 = n0 + wm * 32 + tm * 16 + g;
            if (row0 < NNODES) {
                __half2 v = __floats2half2_rn(acc[tm][tn][0] + bx, acc[tm][tn][1] + by);
                *(__half2*)&g_Th[(size_t)row0 * HIDDEN + col] = v;
            }
            int row1 = row0 + 8;
            if (row1 < NNODES) {
                __half2 v = __floats2half2_rn(acc[tm][tn][2] + bx, acc[tm][tn][3] + by);
                *(__half2*)&g_Th[(size_t)row1 * HIDDEN + col] = v;
            }
        }
    }
}

// ---------------------------------------------------------------------------
// Kernel 2: per edge  logit = W2 . relu(T[src][0:64] + T[dst][64:128]) + b2
// 4 threads per edge; lane l covers cols 16l..16l+15 (32 B fp16). Each edge
// half is 4 lanes x 32 B contiguous = ONE 128-B line.
// ---------------------------------------------------------------------------
__global__ void __launch_bounds__(512)
edge_kernel(const void* __restrict__ eidx_raw,
            const float* __restrict__ W2, const float* __restrict__ b2,
            float* __restrict__ out, int E) {
    __shared__ float sW2[MLPD];
    __shared__ float sB2;
    const int t = threadIdx.x;
    if (t < MLPD) sW2[t] = W2[t];
    else if (t == MLPD) sB2 = *b2;
    __syncthreads();

    const int lane4 = t & 3;
    const int e = blockIdx.x * 128 + (t >> 2);
    if (e >= E) return;

    int offS, offD;
    if (g_is64) {
        const long long* p = (const long long*)eidx_raw;
        offS = (int)p[e] * HIDDEN;
        offD = (int)p[(size_t)E + e] * HIDDEN + MLPD;
    } else {
        const int* p = (const int*)eidx_raw;
        offS = p[e] * HIDDEN;
        offD = p[E + e] * HIDDEN + MLPD;
    }

    const uint4* ps = (const uint4*)&g_Th[offS + lane4 * 16];
    const uint4* pd = (const uint4*)&g_Th[offD + lane4 * 16];
    uint4 sa0 = ps[0], sa1 = ps[1];
    uint4 da0 = pd[0], da1 = pd[1];
    const __half2* sh = (const __half2*)&sa0;   // 8 half2 (sa0,sa1 contiguous regs)
    const __half2* dh = (const __half2*)&da0;

    // h = relu(s + d) in half2, dot in fp32
    const __half2 z2 = __float2half2_rn(0.f);
    float sum = 0.f;
#pragma unroll
    for (int q = 0; q < 4; q++) {
        __half2 hs = __hmax2(__hadd2(sh[q], dh[q]), z2);
        float2 hf = __half22float2(hs);
        float2 w = *(const float2*)&sW2[lane4 * 16 + q * 2];
        sum += hf.x * w.x + hf.y * w.y;
    }
    const __half2* sh1 = (const __half2*)&sa1;
    const __half2* dh1 = (const __half2*)&da1;
#pragma unroll
    for (int q = 0; q < 4; q++) {
        __half2 hs = __hmax2(__hadd2(sh1[q], dh1[q]), z2);
        float2 hf = __half22float2(hs);
        float2 w = *(const float2*)&sW2[lane4 * 16 + 8 + q * 2];
        sum += hf.x * w.x + hf.y * w.y;
    }

    sum += __shfl_down_sync(0xffffffffu, sum, 2, 4);
    sum += __shfl_down_sync(0xffffffffu, sum, 1, 4);

    if (lane4 == 0) out[e] = sum + sB2;
}

// ---------------------------------------------------------------------------
extern "C" void kernel_launch(void* const* d_in, const int* in_sizes, int n_in,
                              void* d_out, int out_size) {
    const float* node_emb = (const float*)d_in[0];
    const void*  eidx     = d_in[1];
    const float* W1       = (const float*)d_in[2];
    const float* b1       = (const float*)d_in[3];
    const float* W2       = (const float*)d_in[4];
    const float* b2       = (const float*)d_in[5];
    float*       out      = (float*)d_out;

    const int twoE = in_sizes[1];
    const int E = twoE / 2;

    const int smem = 4 * 128 * SA * (int)sizeof(__nv_bfloat16)
                   + 2 * HIDDEN * MLPD * (int)sizeof(float);  // 204800 B
    cudaFuncSetAttribute(precompute_kernel,
                         cudaFuncAttributeMaxDynamicSharedMemorySize, smem);

    precompute_kernel<<<(NNODES + 127) / 128, 256, smem>>>(
        node_emb, W1, b1, (const long long*)eidx, twoE);
    edge_kernel<<<(E + 127) / 128, 512>>>(eidx, W2, b2, out, E);
}

// round 13
// speedup vs baseline: 1.0524x; 1.0524x over previous
#include <cuda_runtime.h>
#include <cuda_bf16.h>
#include <cuda_fp16.h>
#include <cstdint>

#define NNODES 50000
#define HIDDEN 128
#define MLPD   64
#define SA 136   // padded bf16 row stride: 8-row ldmatrix steps tile all banks

// Per-node precomputed table (fp16):
//   T[n][0:64]   = emb[n] @ W1[0:128,:]  + b1   (src half, bias folded in)
//   T[n][64:128] = emb[n] @ W1[128:256,:]       (dst half)
__device__ __half g_Th[(size_t)NNODES * HIDDEN];
__device__ int g_is64;   // 1 if edge_index buffer is int64, 0 if int32

__device__ __forceinline__ uint32_t pkbf(__nv_bfloat16 a, __nv_bfloat16 b) {
    __nv_bfloat162 t = __halves2bfloat162(a, b);
    return *reinterpret_cast<uint32_t*>(&t);
}
__device__ __forceinline__ uint32_t smem_u32(const void* p) {
    return (uint32_t)__cvta_generic_to_shared(p);
}
__device__ __forceinline__ void ldsm_x4(uint32_t& r0, uint32_t& r1,
                                        uint32_t& r2, uint32_t& r3, uint32_t addr) {
    asm volatile("ldmatrix.sync.aligned.m8n8.x4.shared.b16 {%0,%1,%2,%3}, [%4];"
                 : "=r"(r0), "=r"(r1), "=r"(r2), "=r"(r3) : "r"(addr));
}
__device__ __forceinline__ void mma16816(float* d, const uint32_t* a, const uint32_t* b) {
    asm volatile(
        "mma.sync.aligned.m16n8k16.row.col.f32.bf16.bf16.f32 "
        "{%0,%1,%2,%3}, {%4,%5,%6,%7}, {%8,%9}, {%0,%1,%2,%3};"
        : "+f"(d[0]), "+f"(d[1]), "+f"(d[2]), "+f"(d[3])
        : "r"(a[0]), "r"(a[1]), "r"(a[2]), "r"(a[3]), "r"(b[0]), "r"(b[1]));
}

// ---------------------------------------------------------------------------
// Kernel 1: T = emb @ Wc (+b1 on cols 0..63) via bf16 3-GEMM split on HMMA.
//   Wc[k][c] = (c<64) ? W1[k][c] : W1[128+k][c-64]
//   T ≈ Eh@Wh + Eh@Wl + El@Wh   (El@Wl dropped, ~2^-18 relative)
// Block: 128 nodes x 128 cols, 256 threads = 8 warps (4m x 2n). fp16 output.
// W converted in-block from (L2-resident) global W1 — no extra launch.
// Block 0 additionally runs the edge-index dtype probe.
// ---------------------------------------------------------------------------
__global__ void __launch_bounds__(256, 1)
precompute_kernel(const float* __restrict__ emb, const float* __restrict__ W1,
                  const float* __restrict__ b1,
                  const long long* __restrict__ eidx64, int twoE) {
    extern __shared__ char smem[];
    __nv_bfloat16* sAh = (__nv_bfloat16*)smem;           // [128][SA]
    __nv_bfloat16* sAl = sAh + 128 * SA;
    __nv_bfloat16* sBh = sAl + 128 * SA;                 // [c=128][SA] (k contiguous)
    __nv_bfloat16* sBl = sBh + 128 * SA;

    const int t = threadIdx.x;
    const int n0 = blockIdx.x * 128;

    // --- dtype probe (block 0 only): 1024 int64 words (8 KB) is in-bounds
    // under both int32 and int64 interpretations of the buffer.
    if (blockIdx.x == 0) {
        __shared__ int ok;
        if (t == 0) ok = 1;
        __syncthreads();
        int n = twoE < 1024 ? twoE : 1024;
        for (int i = t; i < n; i += 256) {
            long long v = eidx64[i];
            if (v < 0 || v >= NNODES) ok = 0;
        }
        __syncthreads();
        if (t == 0) g_is64 = ok;
    }

    // A loader: emb tile -> bf16 hi/lo, rows node-major, k contiguous
    for (int i = t; i < 128 * 32; i += 256) {
        int row = i >> 5, c4 = i & 31;
        int gn = n0 + row;
        float4 v = (gn < NNODES)
            ? *(const float4*)&emb[(size_t)gn * HIDDEN + c4 * 4]
            : make_float4(0.f, 0.f, 0.f, 0.f);
        __nv_bfloat16 hx = __float2bfloat16(v.x), hy = __float2bfloat16(v.y);
        __nv_bfloat16 hz = __float2bfloat16(v.z), hw = __float2bfloat16(v.w);
        __nv_bfloat16 lx = __float2bfloat16(v.x - __bfloat162float(hx));
        __nv_bfloat16 ly = __float2bfloat16(v.y - __bfloat162float(hy));
        __nv_bfloat16 lz = __float2bfloat16(v.z - __bfloat162float(hz));
        __nv_bfloat16 lw = __float2bfloat16(v.w - __bfloat162float(hw));
        *(uint2*)&sAh[row * SA + c4 * 4] = make_uint2(pkbf(hx, hy), pkbf(hz, hw));
        *(uint2*)&sAl[row * SA + c4 * 4] = make_uint2(pkbf(lx, ly), pkbf(lz, lw));
    }
    // B loader: Wc^T hi/lo converted directly from global W1 (coalesced reads)
    for (int i = t; i < 128 * 128; i += 256) {
        int k = i >> 7, c = i & 127;
        float w = (c < MLPD) ? W1[k * MLPD + c] : W1[(HIDDEN + k) * MLPD + (c - MLPD)];
        __nv_bfloat16 h = __float2bfloat16(w);
        sBh[c * SA + k] = h;
        sBl[c * SA + k] = __float2bfloat16(w - __bfloat162float(h));
    }
    __syncthreads();

    const int lane = t & 31;
    const int wid = t >> 5;
    const int wm = wid & 3;   // rows wm*32 .. +32
    const int wn = wid >> 2;  // cols wn*64 .. +64

    const int aRow = lane & 15, aKh = (lane >> 4) * 8;
    const int bN = (lane & 7) + ((lane >> 4) << 3), bKh = ((lane >> 3) & 1) * 8;

    float acc[2][8][4];
#pragma unroll
    for (int tm = 0; tm < 2; tm++)
#pragma unroll
        for (int tn = 0; tn < 8; tn++)
#pragma unroll
            for (int q = 0; q < 4; q++) acc[tm][tn][q] = 0.f;

#pragma unroll
    for (int pass = 0; pass < 3; pass++) {
        const __nv_bfloat16* pA = (pass == 2) ? sAl : sAh;
        const __nv_bfloat16* pB = (pass == 1) ? sBl : sBh;
#pragma unroll
        for (int k0 = 0; k0 < 128; k0 += 16) {
            uint32_t a[2][4], b[8][2];
#pragma unroll
            for (int tm = 0; tm < 2; tm++) {
                uint32_t ad = smem_u32(&pA[(wm * 32 + tm * 16 + aRow) * SA + k0 + aKh]);
                ldsm_x4(a[tm][0], a[tm][1], a[tm][2], a[tm][3], ad);
            }
#pragma unroll
            for (int tp = 0; tp < 4; tp++) {
                uint32_t bd = smem_u32(&pB[(wn * 64 + tp * 16 + bN) * SA + k0 + bKh]);
                ldsm_x4(b[2 * tp][0], b[2 * tp][1], b[2 * tp + 1][0], b[2 * tp + 1][1], bd);
            }
#pragma unroll
            for (int tm = 0; tm < 2; tm++)
#pragma unroll
                for (int tn = 0; tn < 8; tn++)
                    mma16816(acc[tm][tn], a[tm], b[tn]);
        }
    }

    // Epilogue: add b1 on cols<64, store fp16 (half2) to g_Th
    const int g = lane >> 2, tig = lane & 3;
#pragma unroll
    for (int tm = 0; tm < 2; tm++) {
#pragma unroll
        for (int tn = 0; tn < 8; tn++) {
            int col = wn * 64 + tn * 8 + 2 * tig;
            float bx = 0.f, by = 0.f;
            if (wn == 0) { bx = b1[col]; by = b1[col + 1]; }
            int row0 = n0 + wm * 32 + tm * 16 + g;
            if (row0 < NNODES) {
                __half2 v = __floats2half2_rn(acc[tm][tn][0] + bx, acc[tm][tn][1] + by);
                *(__half2*)&g_Th[(size_t)row0 * HIDDEN + col] = v;
            }
            int row1 = row0 + 8;
            if (row1 < NNODES) {
                __half2 v = __floats2half2_rn(acc[tm][tn][2] + bx, acc[tm][tn][3] + by);
                *(__half2*)&g_Th[(size_t)row1 * HIDDEN + col] = v;
            }
        }
    }
}

// ---------------------------------------------------------------------------
// Kernel 2: per edge  logit = W2 . relu(T[src][0:64] + T[dst][64:128]) + b2
// 8 threads per edge; lane l covers cols 8l..8l+7 (16 B fp16). Each edge half
// is 8 lanes x 16 B contiguous = ONE 128-B line = one L1 wavefront.
// ---------------------------------------------------------------------------
__global__ void __launch_bounds__(512)
edge_kernel(const void* __restrict__ eidx_raw,
            const float* __restrict__ W2, const float* __restrict__ b2,
            float* __restrict__ out, int E) {
    __shared__ float sW2[MLPD];
    __shared__ float sB2;
    const int t = threadIdx.x;
    if (t < MLPD) sW2[t] = W2[t];
    else if (t == MLPD) sB2 = *b2;
    __syncthreads();

    const int lane8 = t & 7;
    const int e = blockIdx.x * 64 + (t >> 3);
    if (e >= E) return;

    int offS, offD;
    if (g_is64) {
        const long long* p = (const long long*)eidx_raw;
        offS = (int)p[e] * HIDDEN;
        offD = (int)p[(size_t)E + e] * HIDDEN + MLPD;
    } else {
        const int* p = (const int*)eidx_raw;
        offS = p[e] * HIDDEN;
        offD = p[E + e] * HIDDEN + MLPD;
    }

    uint4 sa = *(const uint4*)&g_Th[offS + lane8 * 8];
    uint4 da = *(const uint4*)&g_Th[offD + lane8 * 8];
    const __half2* sh = (const __half2*)&sa;
    const __half2* dh = (const __half2*)&da;

    // h = relu(s + d) in half2, dot in fp32 (weights read directly from smem)
    const __half2 z2 = __float2half2_rn(0.f);
    float sum = 0.f;
#pragma unroll
    for (int q = 0; q < 4; q++) {
        __half2 hs = __hmax2(__hadd2(sh[q], dh[q]), z2);
        float2 hf = __half22float2(hs);
        float2 w = *(const float2*)&sW2[lane8 * 8 + q * 2];
        sum += hf.x * w.x + hf.y * w.y;
    }

    sum += __shfl_down_sync(0xffffffffu, sum, 4, 8);
    sum += __shfl_down_sync(0xffffffffu, sum, 2, 8);
    sum += __shfl_down_sync(0xffffffffu, sum, 1, 8);

    if (lane8 == 0) out[e] = sum + sB2;
}

// ---------------------------------------------------------------------------
extern "C" void kernel_launch(void* const* d_in, const int* in_sizes, int n_in,
                              void* d_out, int out_size) {
    const float* node_emb = (const float*)d_in[0];
    const void*  eidx     = d_in[1];
    const float* W1       = (const float*)d_in[2];
    const float* b1       = (const float*)d_in[3];
    const float* W2       = (const float*)d_in[4];
    const float* b2       = (const float*)d_in[5];
    float*       out      = (float*)d_out;

    const int twoE = in_sizes[1];
    const int E = twoE / 2;

    const int smem = 4 * 128 * SA * (int)sizeof(__nv_bfloat16);  // 139264 B
    cudaFuncSetAttribute(precompute_kernel,
                         cudaFuncAttributeMaxDynamicSharedMemorySize, smem);

    precompute_kernel<<<(NNODES + 127) / 128, 256, smem>>>(
        node_emb, W1, b1, (const long long*)eidx, twoE);
    edge_kernel<<<(E + 63) / 64, 512>>>(eidx, W2, b2, out, E);
}

// round 14
// speedup vs baseline: 1.1865x; 1.1274x over previous
#include <cuda_runtime.h>
#include <cuda_bf16.h>
#include <cuda_fp16.h>
#include <cstdint>

#define NNODES 50000
#define HIDDEN 128
#define MLPD   64
#define SA 136   // padded bf16 row stride: 8-row ldmatrix steps tile all banks

// Per-node precomputed table (fp16):
//   T[n][0:64]   = emb[n] @ W1[0:128,:]  + b1   (src half, bias folded in)
//   T[n][64:128] = emb[n] @ W1[128:256,:]       (dst half)
__device__ __half g_Th[(size_t)NNODES * HIDDEN];
__device__ int g_is64;   // 1 if edge_index buffer is int64, 0 if int32

__device__ __forceinline__ uint32_t pkbf(__nv_bfloat16 a, __nv_bfloat16 b) {
    __nv_bfloat162 t = __halves2bfloat162(a, b);
    return *reinterpret_cast<uint32_t*>(&t);
}
__device__ __forceinline__ uint32_t smem_u32(const void* p) {
    return (uint32_t)__cvta_generic_to_shared(p);
}
__device__ __forceinline__ void ldsm_x4(uint32_t& r0, uint32_t& r1,
                                        uint32_t& r2, uint32_t& r3, uint32_t addr) {
    asm volatile("ldmatrix.sync.aligned.m8n8.x4.shared.b16 {%0,%1,%2,%3}, [%4];"
                 : "=r"(r0), "=r"(r1), "=r"(r2), "=r"(r3) : "r"(addr));
}
__device__ __forceinline__ void mma16816(float* d, const uint32_t* a, const uint32_t* b) {
    asm volatile(
        "mma.sync.aligned.m16n8k16.row.col.f32.bf16.bf16.f32 "
        "{%0,%1,%2,%3}, {%4,%5,%6,%7}, {%8,%9}, {%0,%1,%2,%3};"
        : "+f"(d[0]), "+f"(d[1]), "+f"(d[2]), "+f"(d[3])
        : "r"(a[0]), "r"(a[1]), "r"(a[2]), "r"(a[3]), "r"(b[0]), "r"(b[1]));
}

// ---------------------------------------------------------------------------
// Kernel 1: T = emb @ Wc (+b1 on cols 0..63) via bf16 3-GEMM split on HMMA.
//   Wc[k][c] = (c<64) ? W1[k][c] : W1[128+k][c-64]
//   T ≈ Eh@Wh + Eh@Wl + El@Wh   (El@Wl dropped, ~2^-18 relative)
// Block: 128 nodes x 128 cols, 512 threads = 16 warps (4m x 4n) for latency
// hiding at 1 block/SM. Warp tile 32 rows x 32 cols. fp16 output.
// W converted in-block from (L2-resident) global W1 — no extra launch.
// Block 0 additionally runs the edge-index dtype probe.
// ---------------------------------------------------------------------------
__global__ void __launch_bounds__(512, 1)
precompute_kernel(const float* __restrict__ emb, const float* __restrict__ W1,
                  const float* __restrict__ b1,
                  const long long* __restrict__ eidx64, int twoE) {
    extern __shared__ char smem[];
    __nv_bfloat16* sAh = (__nv_bfloat16*)smem;           // [128][SA]
    __nv_bfloat16* sAl = sAh + 128 * SA;
    __nv_bfloat16* sBh = sAl + 128 * SA;                 // [c=128][SA] (k contiguous)
    __nv_bfloat16* sBl = sBh + 128 * SA;

    const int t = threadIdx.x;
    const int n0 = blockIdx.x * 128;

    // --- dtype probe (block 0 only): 1024 int64 words (8 KB) is in-bounds
    // under both int32 and int64 interpretations of the buffer.
    if (blockIdx.x == 0) {
        __shared__ int ok;
        if (t == 0) ok = 1;
        __syncthreads();
        int n = twoE < 1024 ? twoE : 1024;
        for (int i = t; i < n; i += 512) {
            long long v = eidx64[i];
            if (v < 0 || v >= NNODES) ok = 0;
        }
        __syncthreads();
        if (t == 0) g_is64 = ok;
    }

    // A loader: emb tile -> bf16 hi/lo, rows node-major, k contiguous
    for (int i = t; i < 128 * 32; i += 512) {
        int row = i >> 5, c4 = i & 31;
        int gn = n0 + row;
        float4 v = (gn < NNODES)
            ? *(const float4*)&emb[(size_t)gn * HIDDEN + c4 * 4]
            : make_float4(0.f, 0.f, 0.f, 0.f);
        __nv_bfloat16 hx = __float2bfloat16(v.x), hy = __float2bfloat16(v.y);
        __nv_bfloat16 hz = __float2bfloat16(v.z), hw = __float2bfloat16(v.w);
        __nv_bfloat16 lx = __float2bfloat16(v.x - __bfloat162float(hx));
        __nv_bfloat16 ly = __float2bfloat16(v.y - __bfloat162float(hy));
        __nv_bfloat16 lz = __float2bfloat16(v.z - __bfloat162float(hz));
        __nv_bfloat16 lw = __float2bfloat16(v.w - __bfloat162float(hw));
        *(uint2*)&sAh[row * SA + c4 * 4] = make_uint2(pkbf(hx, hy), pkbf(hz, hw));
        *(uint2*)&sAl[row * SA + c4 * 4] = make_uint2(pkbf(lx, ly), pkbf(lz, lw));
    }
    // B loader: Wc^T hi/lo converted directly from global W1 (coalesced reads)
    for (int i = t; i < 128 * 128; i += 512) {
        int k = i >> 7, c = i & 127;
        float w = (c < MLPD) ? W1[k * MLPD + c] : W1[(HIDDEN + k) * MLPD + (c - MLPD)];
        __nv_bfloat16 h = __float2bfloat16(w);
        sBh[c * SA + k] = h;
        sBl[c * SA + k] = __float2bfloat16(w - __bfloat162float(h));
    }
    __syncthreads();

    const int lane = t & 31;
    const int wid = t >> 5;
    const int wm = wid & 3;   // rows wm*32 .. +32
    const int wn = wid >> 2;  // cols wn*32 .. +32

    const int aRow = lane & 15, aKh = (lane >> 4) * 8;
    const int bN = (lane & 7) + ((lane >> 4) << 3), bKh = ((lane >> 3) & 1) * 8;

    float acc[2][4][4];
#pragma unroll
    for (int tm = 0; tm < 2; tm++)
#pragma unroll
        for (int tn = 0; tn < 4; tn++)
#pragma unroll
            for (int q = 0; q < 4; q++) acc[tm][tn][q] = 0.f;

#pragma unroll
    for (int pass = 0; pass < 3; pass++) {
        const __nv_bfloat16* pA = (pass == 2) ? sAl : sAh;
        const __nv_bfloat16* pB = (pass == 1) ? sBl : sBh;
#pragma unroll
        for (int k0 = 0; k0 < 128; k0 += 16) {
            uint32_t a[2][4], b[4][2];
#pragma unroll
            for (int tm = 0; tm < 2; tm++) {
                uint32_t ad = smem_u32(&pA[(wm * 32 + tm * 16 + aRow) * SA + k0 + aKh]);
                ldsm_x4(a[tm][0], a[tm][1], a[tm][2], a[tm][3], ad);
            }
#pragma unroll
            for (int tp = 0; tp < 2; tp++) {
                uint32_t bd = smem_u32(&pB[(wn * 32 + tp * 16 + bN) * SA + k0 + bKh]);
                ldsm_x4(b[2 * tp][0], b[2 * tp][1], b[2 * tp + 1][0], b[2 * tp + 1][1], bd);
            }
#pragma unroll
            for (int tm = 0; tm < 2; tm++)
#pragma unroll
                for (int tn = 0; tn < 4; tn++)
                    mma16816(acc[tm][tn], a[tm], b[tn]);
        }
    }

    // Epilogue: add b1 on cols<64, store fp16 (half2) to g_Th
    const int g = lane >> 2, tig = lane & 3;
#pragma unroll
    for (int tm = 0; tm < 2; tm++) {
#pragma unroll
        for (int tn = 0; tn < 4; tn++) {
            int col = wn * 32 + tn * 8 + 2 * tig;
            float bx = 0.f, by = 0.f;
            if (col < MLPD) { bx = b1[col]; by = b1[col + 1]; }
            int row0 = n0 + wm * 32 + tm * 16 + g;
            if (row0 < NNODES) {
                __half2 v = __floats2half2_rn(acc[tm][tn][0] + bx, acc[tm][tn][1] + by);
                *(__half2*)&g_Th[(size_t)row0 * HIDDEN + col] = v;
            }
            int row1 = row0 + 8;
            if (row1 < NNODES) {
                __half2 v = __floats2half2_rn(acc[tm][tn][2] + bx, acc[tm][tn][3] + by);
                *(__half2*)&g_Th[(size_t)row1 * HIDDEN + col] = v;
            }
        }
    }
}

// ---------------------------------------------------------------------------
// Kernel 2 (R10-measured 31.6us): per edge
//   logit = W2 . relu(T[src][0:64] + T[dst][64:128]) + b2
// 4 threads per edge; lane l covers cols 16l..16l+15 (32 B fp16).
// ---------------------------------------------------------------------------
__global__ void __launch_bounds__(512)
edge_kernel(const void* __restrict__ eidx_raw,
            const float* __restrict__ W2, const float* __restrict__ b2,
            float* __restrict__ out, int E) {
    __shared__ float sW2[MLPD];
    __shared__ float sB2;
    const int t = threadIdx.x;
    if (t < MLPD) sW2[t] = W2[t];
    else if (t == MLPD) sB2 = *b2;
    __syncthreads();

    const int lane4 = t & 3;
    const int e = blockIdx.x * 128 + (t >> 2);
    if (e >= E) return;

    int offS, offD;
    if (g_is64) {
        const long long* p = (const long long*)eidx_raw;
        offS = (int)p[e] * HIDDEN;
        offD = (int)p[(size_t)E + e] * HIDDEN + MLPD;
    } else {
        const int* p = (const int*)eidx_raw;
        offS = p[e] * HIDDEN;
        offD = p[E + e] * HIDDEN + MLPD;
    }

    const uint4* ps = (const uint4*)&g_Th[offS + lane4 * 16];
    const uint4* pd = (const uint4*)&g_Th[offD + lane4 * 16];
    uint4 sa0 = ps[0], sa1 = ps[1];
    uint4 da0 = pd[0], da1 = pd[1];
    const __half2* sh = (const __half2*)&sa0;
    const __half2* dh = (const __half2*)&da0;

    const __half2 z2 = __float2half2_rn(0.f);
    float sum = 0.f;
#pragma unroll
    for (int q = 0; q < 4; q++) {
        __half2 hs = __hmax2(__hadd2(sh[q], dh[q]), z2);
        float2 hf = __half22float2(hs);
        float2 w = *(const float2*)&sW2[lane4 * 16 + q * 2];
        sum += hf.x * w.x + hf.y * w.y;
    }
    const __half2* sh1 = (const __half2*)&sa1;
    const __half2* dh1 = (const __half2*)&da1;
#pragma unroll
    for (int q = 0; q < 4; q++) {
        __half2 hs = __hmax2(__hadd2(sh1[q], dh1[q]), z2);
        float2 hf = __half22float2(hs);
        float2 w = *(const float2*)&sW2[lane4 * 16 + 8 + q * 2];
        sum += hf.x * w.x + hf.y * w.y;
    }

    sum += __shfl_down_sync(0xffffffffu, sum, 2, 4);
    sum += __shfl_down_sync(0xffffffffu, sum, 1, 4);

    if (lane4 == 0) out[e] = sum + sB2;
}

// ---------------------------------------------------------------------------
extern "C" void kernel_launch(void* const* d_in, const int* in_sizes, int n_in,
                              void* d_out, int out_size) {
    const float* node_emb = (const float*)d_in[0];
    const void*  eidx     = d_in[1];
    const float* W1       = (const float*)d_in[2];
    const float* b1       = (const float*)d_in[3];
    const float* W2       = (const float*)d_in[4];
    const float* b2       = (const float*)d_in[5];
    float*       out      = (float*)d_out;

    const int twoE = in_sizes[1];
    const int E = twoE / 2;

    const int smem = 4 * 128 * SA * (int)sizeof(__nv_bfloat16);  // 139264 B
    cudaFuncSetAttribute(precompute_kernel,
                         cudaFuncAttributeMaxDynamicSharedMemorySize, smem);

    precompute_kernel<<<(NNODES + 127) / 128, 512, smem>>>(
        node_emb, W1, b1, (const long long*)eidx, twoE);
    edge_kernel<<<(E + 127) / 128, 512>>>(eidx, W2, b2, out, E);
}